// round 11
// baseline (speedup 1.0000x reference)
#include <cuda_runtime.h>

// ChamferDistance_755914244601: B=4, N=M=8192, 3D points.
// Fused single pass; packed f32x2 FFMA2/FADD2 chain produces full distances
// (seed = s1+s2 hoisted per row/colpair). Col mins in registers; row mins via
// STS cand + deferred chunk reduce + uint atomicMin into d_out.
// 2-row interleaved inner loop + 128-reg budget (occ 2) for per-warp ILP.

#define BB 4
#define NN 8192
#define MM 8192
#define BC 256          // cols per block
#define KC 8            // cols per lane
#define NCP (KC / 2)    // colpairs per lane (4)
#define TPB 256
#define NWARP 8
#define CH 128          // rows per chunk
#define RPW (CH / NWARP)        // 16 rows per warp
#define ROWSPLIT 16
#define NROWS (NN / ROWSPLIT)   // 512
#define NCHUNK (NROWS / CH)     // 4
#define NCB (MM / BC)   // 32 col blocks

typedef unsigned long long ull;

static __device__ __forceinline__ ull pk2(float lo, float hi) {
    ull r; asm("mov.b64 %0, {%1, %2};" : "=l"(r) : "f"(lo), "f"(hi)); return r;
}
static __device__ __forceinline__ void upk2(ull v, float& lo, float& hi) {
    asm("mov.b64 {%0, %1}, %2;" : "=f"(lo), "=f"(hi) : "l"(v));
}
static __device__ __forceinline__ ull ffma2(ull a, ull b, ull c) {
    ull d; asm("fma.rn.f32x2 %0, %1, %2, %3;" : "=l"(d) : "l"(a), "l"(b), "l"(c)); return d;
}
static __device__ __forceinline__ ull fadd2(ull a, ull b) {
    ull d; asm("add.rn.f32x2 %0, %1, %2;" : "=l"(d) : "l"(a), "l"(b)); return d;
}

// Seed d_out (B*N + B*M floats) with FLT_MAX bit pattern.
__global__ void init_kernel(unsigned int* __restrict__ out)
{
    const int i = blockIdx.x * blockDim.x + threadIdx.x;
    if (i < BB * NN + BB * MM) out[i] = 0x7F7FFFFFu;   // FLT_MAX
}

__global__ void __launch_bounds__(TPB, 2)
chamfer_fused(const float* __restrict__ x1, const float* __restrict__ x2,
              unsigned int* __restrict__ out)
{
    __shared__ ulonglong2 RA[CH];      // (x,x),(y,y) per row
    __shared__ ulonglong2 RB[CH];      // (z,z),(s1,s1) per row
    __shared__ float4 colsm[BC];       // (-2x,-2y,-2z,s2) per col
    __shared__ union {
        float cand[CH][33];            // row-min candidates (padded stride)
        float colred[NWARP * BC];      // epilogue col-reduce scratch
    } u;

    const int tid  = threadIdx.x;
    const int lane = tid & 31;
    const int w    = tid >> 5;
    const int b     = blockIdx.z;
    const int split = blockIdx.y;
    const int colbase  = blockIdx.x * BC;
    const int rowbase0 = split * NROWS;

    // ---- prologue ----
    if (tid < BC) {
        const float* p = x2 + ((size_t)b * MM + colbase + tid) * 3;
        float x = p[0], y = p[1], z = p[2];
        colsm[tid] = make_float4(-2.0f * x, -2.0f * y, -2.0f * z,
                                 x * x + y * y + z * z);
    }
    if (tid < CH) {   // stage chunk 0
        const float* p = x1 + ((size_t)b * NN + rowbase0 + tid) * 3;
        float x = p[0], y = p[1], z = p[2];
        float s = x * x + y * y + z * z;
        RA[tid] = make_ulonglong2(pk2(x, x), pk2(y, y));
        RB[tid] = make_ulonglong2(pk2(z, z), pk2(s, s));
    }
    __syncthreads();

    // Lane's colpair cache (4 colpairs = 8 cols): 32 registers.
    ull cxx[NCP], cyy[NCP], czz[NCP], cww[NCP];
#pragma unroll
    for (int cp = 0; cp < NCP; cp++) {
        float4 a = colsm[lane * KC + 2 * cp];
        float4 c = colsm[lane * KC + 2 * cp + 1];
        cxx[cp] = pk2(a.x, c.x);
        cyy[cp] = pk2(a.y, c.y);
        czz[cp] = pk2(a.z, c.z);
        cww[cp] = pk2(a.w, c.w);
    }

    float colacc[KC];
#pragma unroll
    for (int j = 0; j < KC; j++) colacc[j] = 3.4e38f;

    // prefetch chunk 1 rows into registers
    float prx = 0.f, pry = 0.f, prz = 0.f;
    if (tid < CH && NCHUNK > 1) {
        const float* p = x1 + ((size_t)b * NN + rowbase0 + CH + tid) * 3;
        prx = p[0]; pry = p[1]; prz = p[2];
    }

    // ---- main loop ----
    for (int ch = 0; ch < NCHUNK; ch++) {
        const int rowbase = rowbase0 + ch * CH;

        // warp w handles rows [w*16, w*16+16), two rows in flight
#pragma unroll 2
        for (int rr = 0; rr < RPW; rr += 2) {
            const int r0 = w * RPW + rr;
            const int r1 = r0 + 1;
            const ulonglong2 ra0 = RA[r0];   // LDS.128 broadcasts
            const ulonglong2 rb0 = RB[r0];
            const ulonglong2 ra1 = RA[r1];
            const ulonglong2 rb1 = RB[r1];
            float a00 = 3.4e38f, a01 = 3.4e38f;   // row r0 accumulators
            float a10 = 3.4e38f, a11 = 3.4e38f;   // row r1 accumulators
#pragma unroll
            for (int cp = 0; cp < NCP; cp++) {
                // full squared distances: (s1+s2) - 2*dot, both rows
                ull s0 = fadd2(cww[cp], rb0.y);
                ull s1 = fadd2(cww[cp], rb1.y);
                ull c0 = ffma2(cxx[cp], ra0.x,
                         ffma2(cyy[cp], ra0.y,
                         ffma2(czz[cp], rb0.x, s0)));
                ull c1 = ffma2(cxx[cp], ra1.x,
                         ffma2(cyy[cp], ra1.y,
                         ffma2(czz[cp], rb1.x, s1)));
                float c0l, c0h, c1l, c1h;
                upk2(c0, c0l, c0h);
                upk2(c1, c1l, c1h);
                colacc[2 * cp]     = fminf(colacc[2 * cp],     fminf(c0l, c1l));
                colacc[2 * cp + 1] = fminf(colacc[2 * cp + 1], fminf(c0h, c1h));
                a00 = fminf(a00, c0l);  a01 = fminf(a01, c0h);
                a10 = fminf(a10, c1l);  a11 = fminf(a11, c1h);
            }
            u.cand[r0][lane] = fminf(a00, a01);
            u.cand[r1][lane] = fminf(a10, a11);
        }
        __syncthreads();   // cand complete; RA/RB reads done

        // chunk row-reduce: 2 threads per row, conflict-free (stride-33 pad)
        {
            const int r = tid >> 1;
            const int h = tid & 1;
            float m = u.cand[r][h * 16 + 0];
#pragma unroll
            for (int i = 1; i < 16; i++)
                m = fminf(m, u.cand[r][h * 16 + i]);
            m = fminf(m, __shfl_xor_sync(0xFFFFFFFFu, m, 1));
            if (h == 0)
                atomicMin(&out[(size_t)b * NN + rowbase + r],
                          __float_as_uint(m));
        }

        // stage next chunk's rows from prefetched registers
        if (tid < CH && ch + 1 < NCHUNK) {
            float s = prx * prx + pry * pry + prz * prz;
            RA[tid] = make_ulonglong2(pk2(prx, prx), pk2(pry, pry));
            RB[tid] = make_ulonglong2(pk2(prz, prz), pk2(s, s));
            if (ch + 2 < NCHUNK) {
                const float* p = x1 + ((size_t)b * NN + rowbase + 2 * CH + tid) * 3;
                prx = p[0]; pry = p[1]; prz = p[2];
            }
        }
        __syncthreads();   // cand consumed + RA/RB restaged
    }

    // ---- epilogue: reduce colacc across the 8 warps ----
#pragma unroll
    for (int j = 0; j < KC; j++)
        u.colred[w * BC + lane * KC + j] = colacc[j];
    __syncthreads();
    {
        float m = u.colred[tid];
#pragma unroll
        for (int ww = 1; ww < NWARP; ww++)
            m = fminf(m, u.colred[ww * BC + tid]);
        atomicMin(&out[(size_t)(BB * NN) + (size_t)b * MM + colbase + tid],
                  __float_as_uint(m));
    }
}

extern "C" void kernel_launch(void* const* d_in, const int* in_sizes, int n_in,
                              void* d_out, int out_size)
{
    const float* xyz1 = (const float*)d_in[0];   // [B, N, 3]
    const float* xyz2 = (const float*)d_in[1];   // [B, M, 3]
    unsigned int* out = (unsigned int*)d_out;

    const int total = BB * NN + BB * MM;
    init_kernel<<<(total + TPB - 1) / TPB, TPB>>>(out);

    dim3 grid(NCB, ROWSPLIT, BB);   // (32, 16, 4) = 2048 blocks
    chamfer_fused<<<grid, TPB>>>(xyz1, xyz2, out);
}

// round 12
// speedup vs baseline: 1.0545x; 1.0545x over previous
#include <cuda_runtime.h>

// ChamferDistance_755914244601: B=4, N=M=8192, 3D points.
// Fused single pass; packed f32x2 FFMA2/FADD2 chain produces full distances.
// Row tile held as scalar float4 (1 LDS.128/row, packed operands built via
// register dup movs); col mins in registers; row mins via STS cand +
// vectorized chunk reduce + uint atomicMin into d_out.

#define BB 4
#define NN 8192
#define MM 8192
#define BC 256          // cols per block
#define KC 8            // cols per lane
#define NCP (KC / 2)    // colpairs per lane (4)
#define TPB 256
#define NWARP 8
#define CH 128          // rows per chunk
#define RPW (CH / NWARP)        // 16 rows per warp
#define ROWSPLIT 16
#define NROWS (NN / ROWSPLIT)   // 512
#define NCHUNK (NROWS / CH)     // 4
#define NCB (MM / BC)   // 32 col blocks
#define CPAD 36         // cand row stride (floats): 144B, 16B-aligned

typedef unsigned long long ull;

static __device__ __forceinline__ ull pk2(float lo, float hi) {
    ull r; asm("mov.b64 %0, {%1, %2};" : "=l"(r) : "f"(lo), "f"(hi)); return r;
}
static __device__ __forceinline__ ull dup2(float v) {
    ull r; asm("mov.b64 %0, {%1, %1};" : "=l"(r) : "f"(v)); return r;
}
static __device__ __forceinline__ void upk2(ull v, float& lo, float& hi) {
    asm("mov.b64 {%0, %1}, %2;" : "=f"(lo), "=f"(hi) : "l"(v));
}
static __device__ __forceinline__ ull ffma2(ull a, ull b, ull c) {
    ull d; asm("fma.rn.f32x2 %0, %1, %2, %3;" : "=l"(d) : "l"(a), "l"(b), "l"(c)); return d;
}
static __device__ __forceinline__ ull fadd2(ull a, ull b) {
    ull d; asm("add.rn.f32x2 %0, %1, %2;" : "=l"(d) : "l"(a), "l"(b)); return d;
}

// Seed d_out (B*N + B*M floats) with FLT_MAX bit pattern.
__global__ void init_kernel(unsigned int* __restrict__ out)
{
    const int i = blockIdx.x * blockDim.x + threadIdx.x;
    if (i < BB * NN + BB * MM) out[i] = 0x7F7FFFFFu;   // FLT_MAX
}

__global__ void __launch_bounds__(TPB, 3)
chamfer_fused(const float* __restrict__ x1, const float* __restrict__ x2,
              unsigned int* __restrict__ out)
{
    __shared__ float4 RS[CH];          // (x, y, z, s1) per row  (2 KB)
    __shared__ float4 colsm[BC];       // (-2x,-2y,-2z,s2) per col (4 KB)
    __shared__ union {
        float  cand[CH][CPAD];         // row-min candidates (18.4 KB)
        float  colred[NWARP * BC];     // epilogue col-reduce scratch (8 KB)
    } u;

    const int tid  = threadIdx.x;
    const int lane = tid & 31;
    const int w    = tid >> 5;
    const int b     = blockIdx.z;
    const int split = blockIdx.y;
    const int colbase  = blockIdx.x * BC;
    const int rowbase0 = split * NROWS;

    // ---- prologue ----
    if (tid < BC) {
        const float* p = x2 + ((size_t)b * MM + colbase + tid) * 3;
        float x = p[0], y = p[1], z = p[2];
        colsm[tid] = make_float4(-2.0f * x, -2.0f * y, -2.0f * z,
                                 x * x + y * y + z * z);
    }
    if (tid < CH) {   // stage chunk 0
        const float* p = x1 + ((size_t)b * NN + rowbase0 + tid) * 3;
        float x = p[0], y = p[1], z = p[2];
        RS[tid] = make_float4(x, y, z, x * x + y * y + z * z);
    }
    __syncthreads();

    // Lane's colpair cache (4 colpairs = 8 cols): 32 registers.
    ull cxx[NCP], cyy[NCP], czz[NCP], cww[NCP];
#pragma unroll
    for (int cp = 0; cp < NCP; cp++) {
        float4 a = colsm[lane * KC + 2 * cp];
        float4 c = colsm[lane * KC + 2 * cp + 1];
        cxx[cp] = pk2(a.x, c.x);
        cyy[cp] = pk2(a.y, c.y);
        czz[cp] = pk2(a.z, c.z);
        cww[cp] = pk2(a.w, c.w);
    }

    float colacc[KC];
#pragma unroll
    for (int j = 0; j < KC; j++) colacc[j] = 3.4e38f;

    // prefetch chunk 1 rows into registers
    float prx = 0.f, pry = 0.f, prz = 0.f;
    if (tid < CH && NCHUNK > 1) {
        const float* p = x1 + ((size_t)b * NN + rowbase0 + CH + tid) * 3;
        prx = p[0]; pry = p[1]; prz = p[2];
    }

    // ---- main loop ----
    for (int ch = 0; ch < NCHUNK; ch++) {
        const int rowbase = rowbase0 + ch * CH;

        // warp w handles rows [w*16, w*16+16) of this chunk
#pragma unroll 4
        for (int rr = 0; rr < RPW; rr++) {
            const int r = w * RPW + rr;
            const float4 rs = RS[r];           // ONE LDS.128 per row
            const ull rx = dup2(rs.x);         // packed duplicates via movs
            const ull ry = dup2(rs.y);
            const ull rz = dup2(rs.z);
            const ull s1 = dup2(rs.w);
            float racc0 = 3.4e38f, racc1 = 3.4e38f;
#pragma unroll
            for (int cp = 0; cp < NCP; cp++) {
                // seed = s1 + s2 (off chain-critical path), then
                // c = seed - 2*dot = full squared distance, both halves
                ull seed = fadd2(cww[cp], s1);
                ull c = ffma2(cxx[cp], rx,
                        ffma2(cyy[cp], ry,
                        ffma2(czz[cp], rz, seed)));
                float cl, chh; upk2(c, cl, chh);
                colacc[2 * cp]     = fminf(colacc[2 * cp], cl);
                colacc[2 * cp + 1] = fminf(colacc[2 * cp + 1], chh);
                racc0 = fminf(racc0, cl);
                racc1 = fminf(racc1, chh);
            }
            u.cand[r][lane] = fminf(racc0, racc1);   // full-distance candidate
        }
        __syncthreads();   // cand complete; RS reads done

        // chunk row-reduce: 2 threads per row, vectorized LDS.128
        {
            const int r = tid >> 1;
            const int h = tid & 1;
            const float4* cf = (const float4*)&u.cand[r][h * 16];
            float4 v0 = cf[0], v1 = cf[1], v2 = cf[2], v3 = cf[3];
            float m0 = fminf(fminf(v0.x, v0.y), fminf(v0.z, v0.w));
            float m1 = fminf(fminf(v1.x, v1.y), fminf(v1.z, v1.w));
            float m2 = fminf(fminf(v2.x, v2.y), fminf(v2.z, v2.w));
            float m3 = fminf(fminf(v3.x, v3.y), fminf(v3.z, v3.w));
            float m  = fminf(fminf(m0, m1), fminf(m2, m3));
            m = fminf(m, __shfl_xor_sync(0xFFFFFFFFu, m, 1));
            if (h == 0)
                atomicMin(&out[(size_t)b * NN + rowbase + r],
                          __float_as_uint(m));
        }

        // stage next chunk's rows from prefetched registers
        if (tid < CH && ch + 1 < NCHUNK) {
            RS[tid] = make_float4(prx, pry, prz,
                                  prx * prx + pry * pry + prz * prz);
            if (ch + 2 < NCHUNK) {
                const float* p = x1 + ((size_t)b * NN + rowbase + 2 * CH + tid) * 3;
                prx = p[0]; pry = p[1]; prz = p[2];
            }
        }
        __syncthreads();   // cand consumed + RS restaged
    }

    // ---- epilogue: reduce colacc across the 8 warps ----
#pragma unroll
    for (int j = 0; j < KC; j++)
        u.colred[w * BC + lane * KC + j] = colacc[j];
    __syncthreads();
    {
        float m = u.colred[tid];
#pragma unroll
        for (int ww = 1; ww < NWARP; ww++)
            m = fminf(m, u.colred[ww * BC + tid]);
        atomicMin(&out[(size_t)(BB * NN) + (size_t)b * MM + colbase + tid],
                  __float_as_uint(m));
    }
}

extern "C" void kernel_launch(void* const* d_in, const int* in_sizes, int n_in,
                              void* d_out, int out_size)
{
    const float* xyz1 = (const float*)d_in[0];   // [B, N, 3]
    const float* xyz2 = (const float*)d_in[1];   // [B, M, 3]
    unsigned int* out = (unsigned int*)d_out;

    const int total = BB * NN + BB * MM;
    init_kernel<<<(total + TPB - 1) / TPB, TPB>>>(out);

    dim3 grid(NCB, ROWSPLIT, BB);   // (32, 16, 4) = 2048 blocks
    chamfer_fused<<<grid, TPB>>>(xyz1, xyz2, out);
}

// round 13
// speedup vs baseline: 1.1199x; 1.0621x over previous
#include <cuda_runtime.h>

// ChamferDistance_755914244601: B=4, N=M=8192, 3D points.
// Fused single pass; packed f32x2 FFMA2/FADD2 chain produces full distances.
// All 512 rows staged once; warps own private row ranges -> ZERO block
// barriers in the main loop (warp-local sync only). Row mins via warp-private
// cand + vectorized reduce + uint atomicMin; col mins in registers.

#define BB 4
#define NN 8192
#define MM 8192
#define BC 256          // cols per block
#define KC 8            // cols per lane
#define NCP (KC / 2)    // colpairs per lane (4)
#define TPB 256
#define NWARP 8
#define ROWSPLIT 16
#define NROWS (NN / ROWSPLIT)   // 512 rows per block, staged once
#define RPWTOT (NROWS / NWARP)  // 64 rows per warp
#define GRP 16                  // rows per reduce group
#define NGRP (RPWTOT / GRP)     // 4 groups
#define NCB (MM / BC)   // 32 col blocks
#define CPAD 36         // cand row stride (floats): 144B, 16B-aligned

typedef unsigned long long ull;

static __device__ __forceinline__ ull pk2(float lo, float hi) {
    ull r; asm("mov.b64 %0, {%1, %2};" : "=l"(r) : "f"(lo), "f"(hi)); return r;
}
static __device__ __forceinline__ ull dup2(float v) {
    ull r; asm("mov.b64 %0, {%1, %1};" : "=l"(r) : "f"(v)); return r;
}
static __device__ __forceinline__ void upk2(ull v, float& lo, float& hi) {
    asm("mov.b64 {%0, %1}, %2;" : "=f"(lo), "=f"(hi) : "l"(v));
}
static __device__ __forceinline__ ull ffma2(ull a, ull b, ull c) {
    ull d; asm("fma.rn.f32x2 %0, %1, %2, %3;" : "=l"(d) : "l"(a), "l"(b), "l"(c)); return d;
}
static __device__ __forceinline__ ull fadd2(ull a, ull b) {
    ull d; asm("add.rn.f32x2 %0, %1, %2;" : "=l"(d) : "l"(a), "l"(b)); return d;
}

// Seed d_out (B*N + B*M floats) with FLT_MAX bit pattern.
__global__ void init_kernel(unsigned int* __restrict__ out)
{
    const int i = blockIdx.x * blockDim.x + threadIdx.x;
    if (i < BB * NN + BB * MM) out[i] = 0x7F7FFFFFu;   // FLT_MAX
}

__global__ void __launch_bounds__(TPB, 3)
chamfer_fused(const float* __restrict__ x1, const float* __restrict__ x2,
              unsigned int* __restrict__ out)
{
    __shared__ float4 RS[NROWS];       // (x, y, z, s1) per row, staged once (8 KB)
    __shared__ float4 colsm[BC];       // (-2x,-2y,-2z,s2) per col (4 KB)
    __shared__ union {
        float cand[NWARP * GRP][CPAD]; // warp-private row-min cand (18.4 KB)
        float colred[NWARP * BC];      // epilogue col-reduce scratch (8 KB)
    } u;

    const int tid  = threadIdx.x;
    const int lane = tid & 31;
    const int w    = tid >> 5;
    const int b     = blockIdx.z;
    const int split = blockIdx.y;
    const int colbase  = blockIdx.x * BC;
    const int rowbase0 = split * NROWS;

    // ---- prologue: stage col tile + ALL 512 rows ----
    {
        const float* p = x2 + ((size_t)b * MM + colbase + tid) * 3;
        float x = p[0], y = p[1], z = p[2];
        colsm[tid] = make_float4(-2.0f * x, -2.0f * y, -2.0f * z,
                                 x * x + y * y + z * z);
    }
#pragma unroll
    for (int rr = 0; rr < NROWS / TPB; rr++) {
        const int r = rr * TPB + tid;
        const float* p = x1 + ((size_t)b * NN + rowbase0 + r) * 3;
        float x = p[0], y = p[1], z = p[2];
        RS[r] = make_float4(x, y, z, x * x + y * y + z * z);
    }
    __syncthreads();   // the ONLY pre-epilogue block barrier

    // Lane's colpair cache (4 colpairs = 8 cols): 32 registers.
    ull cxx[NCP], cyy[NCP], czz[NCP], cww[NCP];
#pragma unroll
    for (int cp = 0; cp < NCP; cp++) {
        float4 a = colsm[lane * KC + 2 * cp];
        float4 c = colsm[lane * KC + 2 * cp + 1];
        cxx[cp] = pk2(a.x, c.x);
        cyy[cp] = pk2(a.y, c.y);
        czz[cp] = pk2(a.z, c.z);
        cww[cp] = pk2(a.w, c.w);
    }

    float colacc[KC];
#pragma unroll
    for (int j = 0; j < KC; j++) colacc[j] = 3.4e38f;

    // ---- main loop: warp-private, no block barriers ----
    // Warp w owns rows [w*64, w*64+64) in 4 groups of 16.
    for (int g = 0; g < NGRP; g++) {
        const int grow = w * RPWTOT + g * GRP;   // first row of this group

#pragma unroll 4
        for (int rr = 0; rr < GRP; rr++) {
            const float4 rs = RS[grow + rr];     // ONE LDS.128 per row
            const ull rx = dup2(rs.x);
            const ull ry = dup2(rs.y);
            const ull rz = dup2(rs.z);
            const ull s1 = dup2(rs.w);
            float racc0 = 3.4e38f, racc1 = 3.4e38f;
#pragma unroll
            for (int cp = 0; cp < NCP; cp++) {
                // c = (s1+s2) - 2*dot = full squared distance, both halves
                ull seed = fadd2(cww[cp], s1);
                ull c = ffma2(cxx[cp], rx,
                        ffma2(cyy[cp], ry,
                        ffma2(czz[cp], rz, seed)));
                float cl, chh; upk2(c, cl, chh);
                colacc[2 * cp]     = fminf(colacc[2 * cp], cl);
                colacc[2 * cp + 1] = fminf(colacc[2 * cp + 1], chh);
                racc0 = fminf(racc0, cl);
                racc1 = fminf(racc1, chh);
            }
            u.cand[w * GRP + rr][lane] = fminf(racc0, racc1);
        }
        __syncwarp();   // cand visible within the warp

        // group row-reduce: 2 lanes per row, vectorized LDS.128
        {
            const int rloc = lane >> 1;          // 0..15
            const int h    = lane & 1;
            const float4* cf = (const float4*)&u.cand[w * GRP + rloc][h * 16];
            float4 v0 = cf[0], v1 = cf[1], v2 = cf[2], v3 = cf[3];
            float m0 = fminf(fminf(v0.x, v0.y), fminf(v0.z, v0.w));
            float m1 = fminf(fminf(v1.x, v1.y), fminf(v1.z, v1.w));
            float m2 = fminf(fminf(v2.x, v2.y), fminf(v2.z, v2.w));
            float m3 = fminf(fminf(v3.x, v3.y), fminf(v3.z, v3.w));
            float m  = fminf(fminf(m0, m1), fminf(m2, m3));
            m = fminf(m, __shfl_xor_sync(0xFFFFFFFFu, m, 1));
            if (h == 0)
                atomicMin(&out[(size_t)b * NN + rowbase0 + grow + rloc],
                          __float_as_uint(m));
        }
        __syncwarp();   // reduce done before cand rows are overwritten
    }

    // ---- epilogue: reduce colacc across the 8 warps ----
    __syncthreads();   // all warps done with cand (union reuse)
#pragma unroll
    for (int j = 0; j < KC; j++)
        u.colred[w * BC + lane * KC + j] = colacc[j];
    __syncthreads();
    {
        float m = u.colred[tid];
#pragma unroll
        for (int ww = 1; ww < NWARP; ww++)
            m = fminf(m, u.colred[ww * BC + tid]);
        atomicMin(&out[(size_t)(BB * NN) + (size_t)b * MM + colbase + tid],
                  __float_as_uint(m));
    }
}

extern "C" void kernel_launch(void* const* d_in, const int* in_sizes, int n_in,
                              void* d_out, int out_size)
{
    const float* xyz1 = (const float*)d_in[0];   // [B, N, 3]
    const float* xyz2 = (const float*)d_in[1];   // [B, M, 3]
    unsigned int* out = (unsigned int*)d_out;

    const int total = BB * NN + BB * MM;
    init_kernel<<<(total + TPB - 1) / TPB, TPB>>>(out);

    dim3 grid(NCB, ROWSPLIT, BB);   // (32, 16, 4) = 2048 blocks
    chamfer_fused<<<grid, TPB>>>(xyz1, xyz2, out);
}